// round 14
// baseline (speedup 1.0000x reference)
#include <cuda_runtime.h>
#include <cuda_bf16.h>
#include <cuda_fp16.h>
#include <math.h>
#include <cstdint>
#include <cstddef>

// ---------------------------------------------------------------------------
// SelfAttention, mma.sync, fp16 Dekker numerics, 2-stream overlap.
// GEMM cores: 256x128 CTA tile, 8 warps as 4x2, warp tile 64x64
// (doubles MMA-per-LDSM ratio; HMMA f32-acc is rt~8 so tensor pipe was
//  issue-starved at 64x32 warp tiles).
//   M' = Wq Wk^T (bf16x3 128x128); y = (16x)(64M')^T (fp16x3 Dekker);
//   S16k = y (16x)^T + 16384 t (fp16x3); vt = (32Wv^T)(16x)+512bv (fp16x1);
//   out = P vt^T / 512 (fp16x1). Softmax arg/16384, FMA-pipe poly exp.
// ---------------------------------------------------------------------------

#define BB 4
#define SEQ 2048
#define EMB 1024

// ------------------------- scratch (static device) -------------------------
__device__ __half        g_xqh[(size_t)BB*SEQ*EMB], g_xql[(size_t)BB*SEQ*EMB];
__device__ __nv_bfloat16 g_wkh[(size_t)EMB*EMB], g_wkl[(size_t)EMB*EMB];
__device__ __nv_bfloat16 g_wqh[(size_t)EMB*EMB], g_wql[(size_t)EMB*EMB];
__device__ __half        g_wvt16[(size_t)EMB*EMB];
__device__ float         g_mp[(size_t)2*EMB*EMB];
__device__ __half        g_m16h[(size_t)EMB*EMB], g_m16l[(size_t)EMB*EMB];
__device__ __half        g_y16h[(size_t)BB*SEQ*EMB], g_y16l[(size_t)BB*SEQ*EMB];
__device__ __half        g_vt16[(size_t)BB*SEQ*EMB];
__device__ float         g_w[EMB];
__device__ float         g_t[BB*SEQ];
__device__ float         g_s[(size_t)BB*SEQ*SEQ];
__device__ __half        g_ph[(size_t)BB*SEQ*SEQ];

// ------------------------- helpers -----------------------------------------
__device__ __forceinline__ uint32_t smem_to_u32(const void* p) {
    uint32_t a;
    asm("{ .reg .u64 t; cvta.to.shared.u64 t, %1; cvt.u32.u64 %0, t; }"
        : "=r"(a) : "l"(p));
    return a;
}
#define SWZ128(o) ((o) ^ (((o) >> 3) & 0x70))

__device__ __forceinline__ void cp16(uint32_t dst, const void* src) {
    unsigned long long g = (unsigned long long)__cvta_generic_to_global(src);
    asm volatile("cp.async.cg.shared.global [%0], [%1], 16;" :: "r"(dst), "l"(g));
}

__device__ __forceinline__ void ldsm4(uint32_t addr, uint32_t* r) {
    asm volatile("ldmatrix.sync.aligned.m8n8.x4.shared.b16 {%0,%1,%2,%3}, [%4];"
                 : "=r"(r[0]), "=r"(r[1]), "=r"(r[2]), "=r"(r[3]) : "r"(addr));
}

__device__ __forceinline__ void mma16816(float* d, const uint32_t* a, const uint32_t* b) {
    asm volatile(
        "mma.sync.aligned.m16n8k16.row.col.f32.bf16.bf16.f32 "
        "{%0,%1,%2,%3}, {%4,%5,%6,%7}, {%8,%9}, {%0,%1,%2,%3};"
        : "+f"(d[0]), "+f"(d[1]), "+f"(d[2]), "+f"(d[3])
        : "r"(a[0]), "r"(a[1]), "r"(a[2]), "r"(a[3]), "r"(b[0]), "r"(b[1]));
}

__device__ __forceinline__ void mma16816h(float* d, const uint32_t* a, const uint32_t* b) {
    asm volatile(
        "mma.sync.aligned.m16n8k16.row.col.f32.f16.f16.f32 "
        "{%0,%1,%2,%3}, {%4,%5,%6,%7}, {%8,%9}, {%0,%1,%2,%3};"
        : "+f"(d[0]), "+f"(d[1]), "+f"(d[2]), "+f"(d[3])
        : "r"(a[0]), "r"(a[1]), "r"(a[2]), "r"(a[3]), "r"(b[0]), "r"(b[1]));
}

// exp(s) for s <= 0, FMA-pipe only (no MUFU).
__device__ __forceinline__ float fast_exp_neg(float s) {
    float t = s * 1.4426950408889634f;
    float r = t + 12582912.0f;
    float n = r - 12582912.0f;
    float f = t - n;
    float p = 1.5403530393381609e-4f;
    p = fmaf(p, f, 1.3333558146428443e-3f);
    p = fmaf(p, f, 9.618129107628477e-3f);
    p = fmaf(p, f, 5.550410866482158e-2f);
    p = fmaf(p, f, 2.402265069591007e-1f);
    p = fmaf(p, f, 6.931471805599453e-1f);
    p = fmaf(p, f, 1.0f);
    int ni = (int)n;
    ni = max(ni, -126);
    float sc = __int_as_float((unsigned)(ni + 127) << 23);
    return p * sc;
}

// ------------------------- conversion kernels ------------------------------
__global__ __launch_bounds__(256)
void split_x_kernel(const float4* __restrict__ in,
                    __half2* __restrict__ hi, __half2* __restrict__ lo, size_t n4)
{
    size_t i = (size_t)blockIdx.x * blockDim.x + threadIdx.x;
    if (i >= n4) return;
    float4 v = in[i];
    float sx = v.x * 16.0f, sy = v.y * 16.0f, sz = v.z * 16.0f, sw = v.w * 16.0f;
    __half hx = __float2half_rn(sx), hy = __float2half_rn(sy);
    __half hz = __float2half_rn(sz), hw = __float2half_rn(sw);
    hi[2*i]   = __half2(hx, hy);
    hi[2*i+1] = __half2(hz, hw);
    lo[2*i]   = __half2(__float2half_rn(sx - __half2float(hx)),
                        __float2half_rn(sy - __half2float(hy)));
    lo[2*i+1] = __half2(__float2half_rn(sz - __half2float(hz)),
                        __float2half_rn(sw - __half2float(hw)));
}

__global__ __launch_bounds__(256)
void split2_kernel(const float4* __restrict__ in0, const float4* __restrict__ in1,
                   __nv_bfloat162* __restrict__ hi0, __nv_bfloat162* __restrict__ lo0,
                   __nv_bfloat162* __restrict__ hi1, __nv_bfloat162* __restrict__ lo1,
                   size_t n4)
{
    size_t i = (size_t)blockIdx.x * blockDim.x + threadIdx.x;
    if (i >= n4) return;
    const float4* in = blockIdx.y ? in1 : in0;
    __nv_bfloat162* hi = blockIdx.y ? hi1 : hi0;
    __nv_bfloat162* lo = blockIdx.y ? lo1 : lo0;
    float4 v = in[i];
    __nv_bfloat16 hx = __float2bfloat16(v.x), hy = __float2bfloat16(v.y);
    __nv_bfloat16 hz = __float2bfloat16(v.z), hw = __float2bfloat16(v.w);
    hi[2*i]   = __nv_bfloat162(hx, hy);
    hi[2*i+1] = __nv_bfloat162(hz, hw);
    lo[2*i]   = __nv_bfloat162(__float2bfloat16(v.x - __bfloat162float(hx)),
                               __float2bfloat16(v.y - __bfloat162float(hy)));
    lo[2*i+1] = __nv_bfloat162(__float2bfloat16(v.z - __bfloat162float(hz)),
                               __float2bfloat16(v.w - __bfloat162float(hw)));
}

__global__ __launch_bounds__(256)
void msum_split_f16(const float4* __restrict__ p0, const float4* __restrict__ p1,
                    __half2* __restrict__ hi, __half2* __restrict__ lo, size_t n4)
{
    size_t i = (size_t)blockIdx.x * blockDim.x + threadIdx.x;
    if (i >= n4) return;
    float4 a = p0[i], b = p1[i];
    float x = (a.x + b.x) * 64.0f, y = (a.y + b.y) * 64.0f;
    float z = (a.z + b.z) * 64.0f, w = (a.w + b.w) * 64.0f;
    __half hx = __float2half_rn(x), hy = __float2half_rn(y);
    __half hz = __float2half_rn(z), hw = __float2half_rn(w);
    hi[2*i]   = __half2(hx, hy);
    hi[2*i+1] = __half2(hz, hw);
    lo[2*i]   = __half2(__float2half_rn(x - __half2float(hx)),
                        __float2half_rn(y - __half2float(hy)));
    lo[2*i+1] = __half2(__float2half_rn(z - __half2float(hz)),
                        __float2half_rn(w - __half2float(hw)));
}

__global__ __launch_bounds__(256)
void transpose_f16(const float* __restrict__ in, __half* __restrict__ oh,
                   int R, int C)
{
    __shared__ float t[32][33];
    const int c0 = blockIdx.x * 32, r0 = blockIdx.y * 32;
    const int tx = threadIdx.x, ty = threadIdx.y;
#pragma unroll
    for (int i = 0; i < 32; i += 8)
        t[ty + i][tx] = in[(size_t)(r0 + ty + i) * C + c0 + tx];
    __syncthreads();
#pragma unroll
    for (int i = 0; i < 32; i += 8) {
        size_t o = (size_t)(c0 + ty + i) * R + r0 + tx;
        oh[o] = __float2half_rn(t[tx][ty + i] * 32.0f);
    }
}

__global__ __launch_bounds__(256)
void wqbk_kernel(const float* __restrict__ Wq, const float* __restrict__ bk,
                 float* __restrict__ w)
{
    const int gw = (blockIdx.x * 256 + threadIdx.x) >> 5;
    const int lane = threadIdx.x & 31;
    if (gw >= EMB) return;
    const float* row = Wq + (size_t)gw * EMB;
    float s = 0.0f;
    for (int a = lane; a < EMB; a += 32) s += row[a] * bk[a];
#pragma unroll
    for (int o = 16; o > 0; o >>= 1) s += __shfl_xor_sync(0xffffffffu, s, o);
    if (lane == 0) w[gw] = s;
}

// t_raw = 16384 * (x @ w)
__global__ __launch_bounds__(256)
void xw_kernel(const float* __restrict__ x, const float* __restrict__ w,
               float* __restrict__ t)
{
    const int gw = (blockIdx.x * 256 + threadIdx.x) >> 5;
    const int lane = threadIdx.x & 31;
    if (gw >= BB * SEQ) return;
    const float* row = x + (size_t)gw * EMB;
    float s = 0.0f;
    for (int e = lane; e < EMB; e += 32) s += row[e] * w[e];
#pragma unroll
    for (int o = 16; o > 0; o >>= 1) s += __shfl_xor_sync(0xffffffffu, s, o);
    if (lane == 0) t[gw] = s * 16384.0f;
}

// ------------------------- softmax (poly exp, fp16 out) --------------------
__global__ __launch_bounds__(256)
void softmax_poly(const float* __restrict__ S, __half2* __restrict__ Ph)
{
    const float4* row = (const float4*)(S + (size_t)blockIdx.x * SEQ);
    __half2* ph = Ph + (size_t)blockIdx.x * (SEQ / 2);
    const int tid = threadIdx.x, lane = tid & 31, wid = tid >> 5;
    __shared__ float red[8];
    __shared__ float bcast;
    const float SINV = 1.0f / 16384.0f;

    float4 a = row[tid];
    float4 b = row[tid + 256];
    float v[8] = {a.x, a.y, a.z, a.w, b.x, b.y, b.z, b.w};

    float m = v[0];
#pragma unroll
    for (int i = 1; i < 8; i++) m = fmaxf(m, v[i]);
#pragma unroll
    for (int o = 16; o > 0; o >>= 1) m = fmaxf(m, __shfl_xor_sync(0xffffffffu, m, o));
    if (lane == 0) red[wid] = m;
    __syncthreads();
    if (tid == 0) {
        float t = red[0];
#pragma unroll
        for (int i = 1; i < 8; i++) t = fmaxf(t, red[i]);
        bcast = t;
    }
    __syncthreads();
    const float rowmax = bcast;

    float e[8];
    float s = 0.0f;
#pragma unroll
    for (int i = 0; i < 8; i++) {
        e[i] = fast_exp_neg((v[i] - rowmax) * SINV);
        s += e[i];
    }
#pragma unroll
    for (int o = 16; o > 0; o >>= 1) s += __shfl_xor_sync(0xffffffffu, s, o);
    __syncthreads();
    if (lane == 0) red[wid] = s;
    __syncthreads();
    if (tid == 0) {
        float t = 0.0f;
#pragma unroll
        for (int i = 0; i < 8; i++) t += red[i];
        bcast = 1.0f / t;
    }
    __syncthreads();
    const float inv = bcast;

#pragma unroll
    for (int i = 0; i < 8; i++) e[i] *= inv;
#pragma unroll
    for (int j = 0; j < 4; j++) {
        const int idx = (j < 2) ? (2 * tid + j) : (512 + 2 * tid + (j - 2));
        ph[idx] = __floats2half2_rn(e[2 * j], e[2 * j + 1]);
    }
}

// ------------------------- bf16x3 GEMM (M' only, 128x128) -------------------
#define MSTG 65536
#define GEMM_SMEM (3 * MSTG + 1024)

__global__ void __launch_bounds__(256, 1)
gemm_bf16x3(const __nv_bfloat16* __restrict__ Ah, const __nv_bfloat16* __restrict__ Al,
            const __nv_bfloat16* __restrict__ Bh, const __nv_bfloat16* __restrict__ Bl,
            float* __restrict__ Cf,
            int N, int K, int ldA, int ldB, size_t sA, size_t sB, size_t sC)
{
    extern __shared__ char smem[];
    const uint32_t sb = (smem_to_u32(smem) + 1023u) & ~1023u;
    const int tid = threadIdx.x;
    const int wid = tid >> 5;
    const int lane = tid & 31;
    const int z = blockIdx.z;
    const int rowBase = blockIdx.y * 128;
    const int colBase = blockIdx.x * 128;
    const int NC = K >> 6;

    const int warpRow = wid & 1;
    const int warpCol = wid >> 1;

    const __nv_bfloat16* aH = Ah + (size_t)z * sA + (size_t)rowBase * ldA;
    const __nv_bfloat16* aL = Al + (size_t)z * sA + (size_t)rowBase * ldA;
    const __nv_bfloat16* bH = Bh + (size_t)z * sB + (size_t)colBase * ldB;
    const __nv_bfloat16* bL = Bl + (size_t)z * sB + (size_t)colBase * ldB;

    const int grow0 = tid >> 3;
    const int kgB   = (tid & 7) * 16;
    const int kgE   = (tid & 7) * 8;

    auto load_chunk = [&](int stage, int chunk) {
        const uint32_t base = sb + stage * MSTG;
        const int koff = chunk * 64 + kgE;
#pragma unroll
        for (int i = 0; i < 4; i++) {
            const int row = grow0 + i * 32;
            const uint32_t so = SWZ128((uint32_t)(row * 128 + kgB));
            cp16(base +         so, aH + (size_t)row * ldA + koff);
            cp16(base + 16384 + so, aL + (size_t)row * ldA + koff);
            cp16(base + 32768 + so, bH + (size_t)row * ldB + koff);
            cp16(base + 49152 + so, bL + (size_t)row * ldB + koff);
        }
        asm volatile("cp.async.commit_group;" ::: "memory");
    };

    float acc[4][4][4];
#pragma unroll
    for (int i = 0; i < 4; i++)
#pragma unroll
        for (int j = 0; j < 4; j++)
#pragma unroll
            for (int l = 0; l < 4; l++) acc[i][j][l] = 0.0f;

    const int aRow = warpRow * 64 + (lane & 15);
    const int aKB  = (lane >> 4) * 16;
    const int bRow = warpCol * 32 + ((lane >> 4) * 8) + (lane & 7);
    const int bKB  = ((lane >> 3) & 1) * 16;

    load_chunk(0, 0);
    if (NC > 1) load_chunk(1, 1);

    int s = 0;
    for (int c = 0; c < NC; c++) {
        if (c + 1 < NC) {
            asm volatile("cp.async.wait_group 1;" ::: "memory");
        } else {
            asm volatile("cp.async.wait_group 0;" ::: "memory");
        }
        __syncthreads();
        if (c + 2 < NC) {
            int s2 = s + 2; if (s2 >= 3) s2 -= 3;
            load_chunk(s2, c + 2);
        }

        const uint32_t st = sb + s * MSTG;
#pragma unroll
        for (int ks = 0; ks < 4; ks++) {
            uint32_t ah[4][4], al[4][4], bh[4][2], bl[4][2];
#pragma unroll
            for (int mt = 0; mt < 4; mt++) {
                const uint32_t sw = SWZ128(
                    (uint32_t)((aRow + mt * 16) * 128 + ks * 32 + aKB));
                ldsm4(st + sw, ah[mt]);
                ldsm4(st + 16384 + sw, al[mt]);
            }
#pragma unroll
            for (int p = 0; p < 2; p++) {
                const uint32_t sw = SWZ128(
                    (uint32_t)((bRow + p * 16) * 128 + ks * 32 + bKB));
                uint32_t t[4];
                ldsm4(st + 32768 + sw, t);
                bh[2*p][0] = t[0]; bh[2*p][1] = t[1];
                bh[2*p+1][0] = t[2]; bh[2*p+1][1] = t[3];
                ldsm4(st + 49152 + sw, t);
                bl[2*p][0] = t[0]; bl[2*p][1] = t[1];
                bl[2*p+1][0] = t[2]; bl[2*p+1][1] = t[3];
            }
#pragma unroll
            for (int mt = 0; mt < 4; mt++)
#pragma unroll
                for (int nt = 0; nt < 4; nt++)
                    mma16816(acc[mt][nt], ah[mt], bh[nt]);
#pragma unroll
            for (int mt = 0; mt < 4; mt++)
#pragma unroll
                for (int nt = 0; nt < 4; nt++)
                    mma16816(acc[mt][nt], ah[mt], bl[nt]);
#pragma unroll
            for (int mt = 0; mt < 4; mt++)
#pragma unroll
                for (int nt = 0; nt < 4; nt++)
                    mma16816(acc[mt][nt], al[mt], bh[nt]);
        }
        if (++s == 3) s = 0;
    }

    const int lr = lane >> 2;
    const int lc = (lane & 3) * 2;
#pragma unroll
    for (int mt = 0; mt < 4; mt++) {
        const int r0 = rowBase + warpRow * 64 + mt * 16 + lr;
#pragma unroll
        for (int nt = 0; nt < 4; nt++) {
            const int c0 = colBase + warpCol * 32 + nt * 8 + lc;
            float* base = Cf + (size_t)z * sC;
            *reinterpret_cast<float2*>(&base[(size_t)r0 * N + c0]) =
                make_float2(acc[mt][nt][0], acc[mt][nt][1]);
            *reinterpret_cast<float2*>(&base[(size_t)(r0 + 8) * N + c0]) =
                make_float2(acc[mt][nt][2], acc[mt][nt][3]);
        }
    }
}

// ------------------------- fp16 GEMM, 256x128 CTA, warp 64x64 ---------------
// PASSES=3: stage Ah(32K) Al(32K) Bh(16K) Bl(16K) = 96KB, 2 stages.
// PASSES=1: stage A(32K) B(16K) = 48KB, 3 stages.
// OUT_MODE: 0 fp32 (acc*oscale [+col bias]), 1 fp16 (+bias[r]*bscale),
//           2 fp16 Dekker pair.  BIAS_MODE: 0 none, 1 col fp32, 2 row scaled.
template <int PASSES, int OUT_MODE, int BIAS_MODE>
__global__ void __launch_bounds__(256, 1)
gemm_f16w(const __half* __restrict__ Ah, const __half* __restrict__ Al,
          const __half* __restrict__ Bh, const __half* __restrict__ Bl,
          const float* __restrict__ bias, float bscale, float oscale,
          float* __restrict__ Cf, __half* __restrict__ Ch, __half* __restrict__ Cl,
          int N, int K, int ldA, int ldB,
          size_t sA, size_t sB, size_t sC, size_t sBias)
{
    constexpr int STG  = (PASSES == 3) ? 98304 : 49152;
    constexpr int OFFAL = 32768;
    constexpr int OFFB  = (PASSES == 3) ? 65536 : 32768;
    constexpr int NST  = (PASSES == 3) ? 2 : 3;
    extern __shared__ char smem[];
    const uint32_t sb = (smem_to_u32(smem) + 1023u) & ~1023u;
    const int tid = threadIdx.x;
    const int wid = tid >> 5;
    const int lane = tid & 31;
    const int z = blockIdx.z;
    const int rowBase = blockIdx.y * 256;
    const int colBase = blockIdx.x * 128;
    const int NC = K >> 6;

    const int warpRow = wid & 3;   // 4 x 64 = 256 rows
    const int warpCol = wid >> 2;  // 2 x 64 = 128 cols

    const __half* aH = Ah + (size_t)z * sA + (size_t)rowBase * ldA;
    const __half* aL = (PASSES == 3) ? (Al + (size_t)z * sA + (size_t)rowBase * ldA) : nullptr;
    const __half* bH = Bh + (size_t)z * sB + (size_t)colBase * ldB;
    const __half* bL = (PASSES == 3) ? (Bl + (size_t)z * sB + (size_t)colBase * ldB) : nullptr;

    const int grow0 = tid >> 3;          // 0..31
    const int kgB   = (tid & 7) * 16;
    const int kgE   = (tid & 7) * 8;

    auto load_chunk = [&](int stage, int chunk) {
        const uint32_t base = sb + stage * STG;
        const int koff = chunk * 64 + kgE;
#pragma unroll
        for (int i = 0; i < 8; i++) {         // A: 256 rows
            const int row = grow0 + i * 32;
            const uint32_t so = SWZ128((uint32_t)(row * 128 + kgB));
            cp16(base + so, aH + (size_t)row * ldA + koff);
            if (PASSES == 3)
                cp16(base + OFFAL + so, aL + (size_t)row * ldA + koff);
        }
#pragma unroll
        for (int i = 0; i < 4; i++) {         // B: 128 rows
            const int row = grow0 + i * 32;
            const uint32_t so = SWZ128((uint32_t)(row * 128 + kgB));
            cp16(base + OFFB + so, bH + (size_t)row * ldB + koff);
            if (PASSES == 3)
                cp16(base + OFFB + 16384 + so, bL + (size_t)row * ldB + koff);
        }
        asm volatile("cp.async.commit_group;" ::: "memory");
    };

    float acc[4][8][4];
#pragma unroll
    for (int i = 0; i < 4; i++)
#pragma unroll
        for (int j = 0; j < 8; j++)
#pragma unroll
            for (int l = 0; l < 4; l++) acc[i][j][l] = 0.0f;

    const int aRow = warpRow * 64 + (lane & 15);
    const int aKB  = (lane >> 4) * 16;
    const int bRow = warpCol * 64 + ((lane >> 4) * 8) + (lane & 7);
    const int bKB  = ((lane >> 3) & 1) * 16;

    if (NST == 2) {
        load_chunk(0, 0);
    } else {
        load_chunk(0, 0);
        if (NC > 1) load_chunk(1, 1);
    }

    int s = 0;
    for (int c = 0; c < NC; c++) {
        if (NST == 2) {
            if (c + 1 < NC) {
                load_chunk(s ^ 1, c + 1);
                asm volatile("cp.async.wait_group 1;" ::: "memory");
            } else {
                asm volatile("cp.async.wait_group 0;" ::: "memory");
            }
            __syncthreads();
        } else {
            if (c + 1 < NC) {
                asm volatile("cp.async.wait_group 1;" ::: "memory");
            } else {
                asm volatile("cp.async.wait_group 0;" ::: "memory");
            }
            __syncthreads();
            if (c + 2 < NC) {
                int s2 = s + 2; if (s2 >= 3) s2 -= 3;
                load_chunk(s2, c + 2);
            }
        }

        const uint32_t st = sb + s * STG;
#pragma unroll
        for (int ks = 0; ks < 4; ks++) {
            if (PASSES == 3) {
                uint32_t bh[8][2], bl[8][2];
#pragma unroll
                for (int p = 0; p < 4; p++) {
                    const uint32_t sw = SWZ128(
                        (uint32_t)((bRow + p * 16) * 128 + ks * 32 + bKB));
                    uint32_t t[4];
                    ldsm4(st + OFFB + sw, t);
                    bh[2*p][0] = t[0]; bh[2*p][1] = t[1];
                    bh[2*p+1][0] = t[2]; bh[2*p+1][1] = t[3];
                    ldsm4(st + OFFB + 16384 + sw, t);
                    bl[2*p][0] = t[0]; bl[2*p][1] = t[1];
                    bl[2*p+1][0] = t[2]; bl[2*p+1][1] = t[3];
                }
#pragma unroll
                for (int mt = 0; mt < 4; mt++) {
                    const uint32_t sw = SWZ128(
                        (uint32_t)((aRow + mt * 16) * 128 + ks * 32 + aKB));
                    uint32_t ah[4], al[4];
                    ldsm4(st + sw, ah);
                    ldsm4(st + OFFAL + sw, al);
#pragma unroll
                    for (int nt = 0; nt < 8; nt++)
                        mma16816h(acc[mt][nt], ah, bh[nt]);
#pragma unroll
                    for (int nt = 0; nt < 8; nt++)
                        mma16816h(acc[mt][nt], ah, bl[nt]);
#pragma unroll
                    for (int nt = 0; nt < 8; nt++)
                        mma16816h(acc[mt][nt], al, bh[nt]);
                }
            } else {
                uint32_t bfr[8][2];
#pragma unroll
                for (int p = 0; p < 4; p++) {
                    const uint32_t sw = SWZ128(
                        (uint32_t)((bRow + p * 16) * 128 + ks * 32 + bKB));
                    uint32_t t[4];
                    ldsm4(st + OFFB + sw, t);
                    bfr[2*p][0] = t[0]; bfr[2*p][1] = t[1];
                    bfr[2*p+1][0] = t[2]; bfr[2*p+1][1] = t[3];
                }
#pragma unroll
                for (int mt = 0; mt < 4; mt++) {
                    const uint32_t sw = SWZ128(
                        (uint32_t)((aRow + mt * 16) * 128 + ks * 32 + aKB));
                    uint32_t ah[4];
                    ldsm4(st + sw, ah);
#pragma unroll
                    for (int nt = 0; nt < 8; nt++)
                        mma16816h(acc[mt][nt], ah, bfr[nt]);
                }
            }
        }
        if (NST == 2) {
            __syncthreads();
            s ^= 1;
        } else {
            if (++s == 3) s = 0;
        }
    }

    const int lr = lane >> 2;
    const int lc = (lane & 3) * 2;
#pragma unroll
    for (int mt = 0; mt < 4; mt++) {
        const int r0 = rowBase + warpRow * 64 + mt * 16 + lr;
#pragma unroll
        for (int nt = 0; nt < 8; nt++) {
            const int c0 = colBase + warpCol * 64 + nt * 8 + lc;
            float v0 = acc[mt][nt][0], v1 = acc[mt][nt][1];
            float v2 = acc[mt][nt][2], v3 = acc[mt][nt][3];
            if (OUT_MODE == 0) {
                v0 *= oscale; v1 *= oscale; v2 *= oscale; v3 *= oscale;
                if (BIAS_MODE == 1) {
                    const float b0 = bias[z * sBias + c0];
                    const float b1 = bias[z * sBias + c0 + 1];
                    v0 += b0; v1 += b1; v2 += b0; v3 += b1;
                }
                float* base = Cf + (size_t)z * sC;
                *reinterpret_cast<float2*>(&base[(size_t)r0 * N + c0]) =
                    make_float2(v0, v1);
                *reinterpret_cast<float2*>(&base[(size_t)(r0 + 8) * N + c0]) =
                    make_float2(v2, v3);
            } else if (OUT_MODE == 1) {
                if (BIAS_MODE == 2) {
                    const float br0 = bias[r0] * bscale;
                    const float br8 = bias[r0 + 8] * bscale;
                    v0 += br0; v1 += br0; v2 += br8; v3 += br8;
                }
                __half* base = Ch + (size_t)z * sC;
                *reinterpret_cast<__half2*>(&base[(size_t)r0 * N + c0]) =
                    __floats2half2_rn(v0, v1);
                *reinterpret_cast<__half2*>(&base[(size_t)(r0 + 8) * N + c0]) =
                    __floats2half2_rn(v2, v3);
            } else {
                __half h0 = __float2half_rn(v0), h1 = __float2half_rn(v1);
                __half h2 = __float2half_rn(v2), h3 = __float2half_rn(v3);
                __half* chb = Ch + (size_t)z * sC;
                __half* clb = Cl + (size_t)z * sC;
                *reinterpret_cast<__half2*>(&chb[(size_t)r0 * N + c0]) =
                    __half2(h0, h1);
                *reinterpret_cast<__half2*>(&chb[(size_t)(r0 + 8) * N + c0]) =
                    __half2(h2, h3);
                *reinterpret_cast<__half2*>(&clb[(size_t)r0 * N + c0]) =
                    __half2(__float2half_rn(v0 - __half2float(h0)),
                            __float2half_rn(v1 - __half2float(h1)));
                *reinterpret_cast<__half2*>(&clb[(size_t)(r0 + 8) * N + c0]) =
                    __half2(__float2half_rn(v2 - __half2float(h2)),
                            __float2half_rn(v3 - __half2float(h3)));
            }
        }
    }
}

// ------------------------- launch ------------------------------------------
extern "C" void kernel_launch(void* const* d_in, const int* in_sizes, int n_in,
                              void* d_out, int out_size)
{
    (void)in_sizes; (void)n_in; (void)out_size;
    const float* x  = (const float*)d_in[0];
    const float* Wk = (const float*)d_in[1];
    const float* bk = (const float*)d_in[2];
    const float* Wq = (const float*)d_in[3];
    const float* bq = (const float*)d_in[4];  (void)bq;
    const float* Wv = (const float*)d_in[5];
    const float* bv = (const float*)d_in[6];
    float* out = (float*)d_out;

    __nv_bfloat16 *wkh, *wkl, *wqh, *wql;
    __half *xqh, *xql, *wvt16, *m16h, *m16l, *y16h, *y16l, *vt16, *ph;
    float *mp, *wv_, *tv, *sf;
    cudaGetSymbolAddress((void**)&xqh, g_xqh);   cudaGetSymbolAddress((void**)&xql, g_xql);
    cudaGetSymbolAddress((void**)&wkh, g_wkh);   cudaGetSymbolAddress((void**)&wkl, g_wkl);
    cudaGetSymbolAddress((void**)&wqh, g_wqh);   cudaGetSymbolAddress((void**)&wql, g_wql);
    cudaGetSymbolAddress((void**)&wvt16, g_wvt16);
    cudaGetSymbolAddress((void**)&mp, g_mp);
    cudaGetSymbolAddress((void**)&m16h, g_m16h); cudaGetSymbolAddress((void**)&m16l, g_m16l);
    cudaGetSymbolAddress((void**)&y16h, g_y16h); cudaGetSymbolAddress((void**)&y16l, g_y16l);
    cudaGetSymbolAddress((void**)&vt16, g_vt16);
    cudaGetSymbolAddress((void**)&wv_, g_w);     cudaGetSymbolAddress((void**)&tv, g_t);
    cudaGetSymbolAddress((void**)&sf, g_s);
    cudaGetSymbolAddress((void**)&ph, g_ph);

    cudaFuncSetAttribute(gemm_bf16x3, cudaFuncAttributeMaxDynamicSharedMemorySize, GEMM_SMEM);
    cudaFuncSetAttribute((const void*)gemm_f16w<1,1,2>,
                         cudaFuncAttributeMaxDynamicSharedMemorySize, 3 * 49152 + 1024);
    cudaFuncSetAttribute((const void*)gemm_f16w<1,0,0>,
                         cudaFuncAttributeMaxDynamicSharedMemorySize, 3 * 49152 + 1024);
    cudaFuncSetAttribute((const void*)gemm_f16w<3,2,0>,
                         cudaFuncAttributeMaxDynamicSharedMemorySize, 2 * 98304 + 1024);
    cudaFuncSetAttribute((const void*)gemm_f16w<3,0,1>,
                         cudaFuncAttributeMaxDynamicSharedMemorySize, 2 * 98304 + 1024);

    static cudaStream_t sB = nullptr;
    static cudaEvent_t eA = nullptr, eB = nullptr;
    static bool multi = false;
    static bool tried = false;
    if (!tried) {
        tried = true;
        if (cudaStreamCreateWithFlags(&sB, cudaStreamNonBlocking) == cudaSuccess &&
            cudaEventCreateWithFlags(&eA, cudaEventDisableTiming) == cudaSuccess &&
            cudaEventCreateWithFlags(&eB, cudaEventDisableTiming) == cudaSuccess)
            multi = true;
    }
    cudaStream_t s1 = multi ? sB : (cudaStream_t)0;

    const int Mflat = BB * SEQ;  // 8192
    const size_t w4 = (size_t)EMB * EMB / 4;
    const size_t sXB = (size_t)SEQ * EMB;
    const size_t sSB = (size_t)SEQ * SEQ;

    // ---- stream A: x split ----
    {
        size_t n4 = (size_t)Mflat * EMB / 4;
        split_x_kernel<<<(unsigned)((n4 + 255) / 256), 256>>>(
            (const float4*)x, (__half2*)xqh, (__half2*)xql, n4);
    }
    if (multi) {
        cudaEventRecord(eA, 0);
        cudaStreamWaitEvent(sB, eA, 0);
    }

    // ---- stream B: Wv transpose, wqbk, vproj, xw ----
    transpose_f16<<<dim3(32, 32, 1), dim3(32, 8), 0, s1>>>(Wv, wvt16, EMB, EMB);
    wqbk_kernel<<<EMB * 32 / 256, 256, 0, s1>>>(Wq, bk, wv_);
    gemm_f16w<1,1,2><<<dim3(16, 4, BB), 256, 3 * 49152 + 1024, s1>>>(
        wvt16, nullptr, xqh, nullptr, bv, 512.0f, 1.0f,
        nullptr, vt16, nullptr,
        SEQ, EMB, EMB, EMB, 0, sXB, (size_t)EMB * SEQ, 0);
    xw_kernel<<<Mflat * 32 / 256, 256, 0, s1>>>(x, wv_, tv);
    if (multi) cudaEventRecord(eB, sB);

    // ---- stream A: Wk/Wq split -> M' -> msum -> y ----
    split2_kernel<<<dim3((unsigned)((w4 + 255) / 256), 2), 256>>>(
        (const float4*)Wk, (const float4*)Wq,
        (__nv_bfloat162*)wkh, (__nv_bfloat162*)wkl,
        (__nv_bfloat162*)wqh, (__nv_bfloat162*)wql, w4);
    gemm_bf16x3<<<dim3(8, 8, 2), 256, GEMM_SMEM>>>(
        wqh, wql, wkh, wkl, mp,
        EMB, 512, EMB, EMB, 512, 512, (size_t)EMB * EMB);
    msum_split_f16<<<(unsigned)((w4 + 255) / 256), 256>>>(
        (const float4*)mp, (const float4*)(mp + (size_t)EMB * EMB),
        (__half2*)m16h, (__half2*)m16l, w4);
    gemm_f16w<3,2,0><<<dim3(8, 32, 1), 256, 2 * 98304 + 1024>>>(
        xqh, xql, m16h, m16l, nullptr, 0.0f, 1.0f,
        nullptr, y16h, y16l,
        EMB, EMB, EMB, EMB, 0, 0, 0, 0);

    // ---- join ----
    if (multi) cudaStreamWaitEvent(0, eB, 0);

    gemm_f16w<3,0,1><<<dim3(16, 8, BB), 256, 2 * 98304 + 1024>>>(
        y16h, y16l, xqh, xql, tv, 0.0f, 1.0f,
        sf, nullptr, nullptr,
        SEQ, EMB, EMB, EMB, sXB, sXB, sSB, SEQ);
    softmax_poly<<<BB * SEQ, 256>>>(sf, (__half2*)ph);
    gemm_f16w<1,0,0><<<dim3(8, 8, BB), 256, 3 * 49152 + 1024>>>(
        ph, nullptr, vt16, nullptr, nullptr, 0.0f, 1.0f / 512.0f,
        out, nullptr, nullptr,
        EMB, SEQ, SEQ, SEQ, sSB, (size_t)EMB * SEQ, sXB, 0);
}

// round 16
// speedup vs baseline: 1.0671x; 1.0671x over previous
#include <cuda_runtime.h>
#include <cuda_bf16.h>
#include <cuda_fp16.h>
#include <math.h>
#include <cstdint>
#include <cstddef>

// ---------------------------------------------------------------------------
// SelfAttention, mma.sync GEMMs (R12 cores), fp16 Dekker numerics,
// 2-stream schedule (all side-stream work forked via events, capture-legal):
//   A: split2 -> M' -> msum -> (wait eX) y -> (wait eB) S -> sm0 -> PV0
//   B: (wait e0) split_x -> Wv transpose -> wqbk -> vproj -> xw
//      (wait eSm0) sm1 -> PV1
// ---------------------------------------------------------------------------

#define BB 4
#define SEQ 2048
#define EMB 1024

// ------------------------- scratch (static device) -------------------------
__device__ __half        g_xqh[(size_t)BB*SEQ*EMB], g_xql[(size_t)BB*SEQ*EMB];
__device__ __nv_bfloat16 g_wkh[(size_t)EMB*EMB], g_wkl[(size_t)EMB*EMB];
__device__ __nv_bfloat16 g_wqh[(size_t)EMB*EMB], g_wql[(size_t)EMB*EMB];
__device__ __half        g_wvt16[(size_t)EMB*EMB];
__device__ float         g_mp[(size_t)2*EMB*EMB];
__device__ __half        g_m16h[(size_t)EMB*EMB], g_m16l[(size_t)EMB*EMB];
__device__ __half        g_y16h[(size_t)BB*SEQ*EMB], g_y16l[(size_t)BB*SEQ*EMB];
__device__ __half        g_vt16[(size_t)BB*SEQ*EMB];
__device__ float         g_w[EMB];
__device__ float         g_t[BB*SEQ];
__device__ float         g_s[(size_t)BB*SEQ*SEQ];
__device__ __half        g_ph[(size_t)BB*SEQ*SEQ];

// ------------------------- helpers -----------------------------------------
__device__ __forceinline__ uint32_t smem_to_u32(const void* p) {
    uint32_t a;
    asm("{ .reg .u64 t; cvta.to.shared.u64 t, %1; cvt.u32.u64 %0, t; }"
        : "=r"(a) : "l"(p));
    return a;
}
#define SWZ128(o) ((o) ^ (((o) >> 3) & 0x70))

__device__ __forceinline__ void cp16(uint32_t dst, const void* src) {
    unsigned long long g = (unsigned long long)__cvta_generic_to_global(src);
    asm volatile("cp.async.cg.shared.global [%0], [%1], 16;" :: "r"(dst), "l"(g));
}

__device__ __forceinline__ void ldsm4(uint32_t addr, uint32_t* r) {
    asm volatile("ldmatrix.sync.aligned.m8n8.x4.shared.b16 {%0,%1,%2,%3}, [%4];"
                 : "=r"(r[0]), "=r"(r[1]), "=r"(r[2]), "=r"(r[3]) : "r"(addr));
}

__device__ __forceinline__ void mma16816(float* d, const uint32_t* a, const uint32_t* b) {
    asm volatile(
        "mma.sync.aligned.m16n8k16.row.col.f32.bf16.bf16.f32 "
        "{%0,%1,%2,%3}, {%4,%5,%6,%7}, {%8,%9}, {%0,%1,%2,%3};"
        : "+f"(d[0]), "+f"(d[1]), "+f"(d[2]), "+f"(d[3])
        : "r"(a[0]), "r"(a[1]), "r"(a[2]), "r"(a[3]), "r"(b[0]), "r"(b[1]));
}

__device__ __forceinline__ void mma16816h(float* d, const uint32_t* a, const uint32_t* b) {
    asm volatile(
        "mma.sync.aligned.m16n8k16.row.col.f32.f16.f16.f32 "
        "{%0,%1,%2,%3}, {%4,%5,%6,%7}, {%8,%9}, {%0,%1,%2,%3};"
        : "+f"(d[0]), "+f"(d[1]), "+f"(d[2]), "+f"(d[3])
        : "r"(a[0]), "r"(a[1]), "r"(a[2]), "r"(a[3]), "r"(b[0]), "r"(b[1]));
}

// exp(s) for s <= 0, FMA-pipe only (no MUFU).
__device__ __forceinline__ float fast_exp_neg(float s) {
    float t = s * 1.4426950408889634f;
    float r = t + 12582912.0f;
    float n = r - 12582912.0f;
    float f = t - n;
    float p = 1.5403530393381609e-4f;
    p = fmaf(p, f, 1.3333558146428443e-3f);
    p = fmaf(p, f, 9.618129107628477e-3f);
    p = fmaf(p, f, 5.550410866482158e-2f);
    p = fmaf(p, f, 2.402265069591007e-1f);
    p = fmaf(p, f, 6.931471805599453e-1f);
    p = fmaf(p, f, 1.0f);
    int ni = (int)n;
    ni = max(ni, -126);
    float sc = __int_as_float((unsigned)(ni + 127) << 23);
    return p * sc;
}

// ------------------------- conversion kernels ------------------------------
__global__ __launch_bounds__(256)
void split_x_kernel(const float4* __restrict__ in,
                    __half2* __restrict__ hi, __half2* __restrict__ lo, size_t n4)
{
    size_t i = (size_t)blockIdx.x * blockDim.x + threadIdx.x;
    if (i >= n4) return;
    float4 v = in[i];
    float sx = v.x * 16.0f, sy = v.y * 16.0f, sz = v.z * 16.0f, sw = v.w * 16.0f;
    __half hx = __float2half_rn(sx), hy = __float2half_rn(sy);
    __half hz = __float2half_rn(sz), hw = __float2half_rn(sw);
    hi[2*i]   = __half2(hx, hy);
    hi[2*i+1] = __half2(hz, hw);
    lo[2*i]   = __half2(__float2half_rn(sx - __half2float(hx)),
                        __float2half_rn(sy - __half2float(hy)));
    lo[2*i+1] = __half2(__float2half_rn(sz - __half2float(hz)),
                        __float2half_rn(sw - __half2float(hw)));
}

__global__ __launch_bounds__(256)
void split2_kernel(const float4* __restrict__ in0, const float4* __restrict__ in1,
                   __nv_bfloat162* __restrict__ hi0, __nv_bfloat162* __restrict__ lo0,
                   __nv_bfloat162* __restrict__ hi1, __nv_bfloat162* __restrict__ lo1,
                   size_t n4)
{
    size_t i = (size_t)blockIdx.x * blockDim.x + threadIdx.x;
    if (i >= n4) return;
    const float4* in = blockIdx.y ? in1 : in0;
    __nv_bfloat162* hi = blockIdx.y ? hi1 : hi0;
    __nv_bfloat162* lo = blockIdx.y ? lo1 : lo0;
    float4 v = in[i];
    __nv_bfloat16 hx = __float2bfloat16(v.x), hy = __float2bfloat16(v.y);
    __nv_bfloat16 hz = __float2bfloat16(v.z), hw = __float2bfloat16(v.w);
    hi[2*i]   = __nv_bfloat162(hx, hy);
    hi[2*i+1] = __nv_bfloat162(hz, hw);
    lo[2*i]   = __nv_bfloat162(__float2bfloat16(v.x - __bfloat162float(hx)),
                               __float2bfloat16(v.y - __bfloat162float(hy)));
    lo[2*i+1] = __nv_bfloat162(__float2bfloat16(v.z - __bfloat162float(hz)),
                               __float2bfloat16(v.w - __bfloat162float(hw)));
}

__global__ __launch_bounds__(256)
void msum_split_f16(const float4* __restrict__ p0, const float4* __restrict__ p1,
                    __half2* __restrict__ hi, __half2* __restrict__ lo, size_t n4)
{
    size_t i = (size_t)blockIdx.x * blockDim.x + threadIdx.x;
    if (i >= n4) return;
    float4 a = p0[i], b = p1[i];
    float x = (a.x + b.x) * 64.0f, y = (a.y + b.y) * 64.0f;
    float z = (a.z + b.z) * 64.0f, w = (a.w + b.w) * 64.0f;
    __half hx = __float2half_rn(x), hy = __float2half_rn(y);
    __half hz = __float2half_rn(z), hw = __float2half_rn(w);
    hi[2*i]   = __half2(hx, hy);
    hi[2*i+1] = __half2(hz, hw);
    lo[2*i]   = __half2(__float2half_rn(x - __half2float(hx)),
                        __float2half_rn(y - __half2float(hy)));
    lo[2*i+1] = __half2(__float2half_rn(z - __half2float(hz)),
                        __float2half_rn(w - __half2float(hw)));
}

__global__ __launch_bounds__(256)
void transpose_f16(const float* __restrict__ in, __half* __restrict__ oh,
                   int R, int C)
{
    __shared__ float t[32][33];
    const int c0 = blockIdx.x * 32, r0 = blockIdx.y * 32;
    const int tx = threadIdx.x, ty = threadIdx.y;
#pragma unroll
    for (int i = 0; i < 32; i += 8)
        t[ty + i][tx] = in[(size_t)(r0 + ty + i) * C + c0 + tx];
    __syncthreads();
#pragma unroll
    for (int i = 0; i < 32; i += 8) {
        size_t o = (size_t)(c0 + ty + i) * R + r0 + tx;
        oh[o] = __float2half_rn(t[tx][ty + i] * 32.0f);
    }
}

__global__ __launch_bounds__(256)
void wqbk_kernel(const float* __restrict__ Wq, const float* __restrict__ bk,
                 float* __restrict__ w)
{
    const int gw = (blockIdx.x * 256 + threadIdx.x) >> 5;
    const int lane = threadIdx.x & 31;
    if (gw >= EMB) return;
    const float* row = Wq + (size_t)gw * EMB;
    float s = 0.0f;
    for (int a = lane; a < EMB; a += 32) s += row[a] * bk[a];
#pragma unroll
    for (int o = 16; o > 0; o >>= 1) s += __shfl_xor_sync(0xffffffffu, s, o);
    if (lane == 0) w[gw] = s;
}

// t_raw = 16384 * (x @ w)
__global__ __launch_bounds__(256)
void xw_kernel(const float* __restrict__ x, const float* __restrict__ w,
               float* __restrict__ t)
{
    const int gw = (blockIdx.x * 256 + threadIdx.x) >> 5;
    const int lane = threadIdx.x & 31;
    if (gw >= BB * SEQ) return;
    const float* row = x + (size_t)gw * EMB;
    float s = 0.0f;
    for (int e = lane; e < EMB; e += 32) s += row[e] * w[e];
#pragma unroll
    for (int o = 16; o > 0; o >>= 1) s += __shfl_xor_sync(0xffffffffu, s, o);
    if (lane == 0) t[gw] = s * 16384.0f;
}

// ------------------------- softmax (poly exp, fp16 out) --------------------
__global__ __launch_bounds__(256)
void softmax_poly(const float* __restrict__ S, __half2* __restrict__ Ph)
{
    const float4* row = (const float4*)(S + (size_t)blockIdx.x * SEQ);
    __half2* ph = Ph + (size_t)blockIdx.x * (SEQ / 2);
    const int tid = threadIdx.x, lane = tid & 31, wid = tid >> 5;
    __shared__ float red[8];
    __shared__ float bcast;
    const float SINV = 1.0f / 16384.0f;

    float4 a = row[tid];
    float4 b = row[tid + 256];
    float v[8] = {a.x, a.y, a.z, a.w, b.x, b.y, b.z, b.w};

    float m = v[0];
#pragma unroll
    for (int i = 1; i < 8; i++) m = fmaxf(m, v[i]);
#pragma unroll
    for (int o = 16; o > 0; o >>= 1) m = fmaxf(m, __shfl_xor_sync(0xffffffffu, m, o));
    if (lane == 0) red[wid] = m;
    __syncthreads();
    if (tid == 0) {
        float t = red[0];
#pragma unroll
        for (int i = 1; i < 8; i++) t = fmaxf(t, red[i]);
        bcast = t;
    }
    __syncthreads();
    const float rowmax = bcast;

    float e[8];
    float s = 0.0f;
#pragma unroll
    for (int i = 0; i < 8; i++) {
        e[i] = fast_exp_neg((v[i] - rowmax) * SINV);
        s += e[i];
    }
#pragma unroll
    for (int o = 16; o > 0; o >>= 1) s += __shfl_xor_sync(0xffffffffu, s, o);
    __syncthreads();
    if (lane == 0) red[wid] = s;
    __syncthreads();
    if (tid == 0) {
        float t = 0.0f;
#pragma unroll
        for (int i = 0; i < 8; i++) t += red[i];
        bcast = 1.0f / t;
    }
    __syncthreads();
    const float inv = bcast;

#pragma unroll
    for (int i = 0; i < 8; i++) e[i] *= inv;
#pragma unroll
    for (int j = 0; j < 4; j++) {
        const int idx = (j < 2) ? (2 * tid + j) : (512 + 2 * tid + (j - 2));
        ph[idx] = __floats2half2_rn(e[2 * j], e[2 * j + 1]);
    }
}

// ------------------------- bf16x3 GEMM (M' only) ----------------------------
#define STAGE_BYTES 65536
#define GEMM_SMEM (3 * STAGE_BYTES + 1024)

__global__ void __launch_bounds__(256, 1)
gemm_bf16x3(const __nv_bfloat16* __restrict__ Ah, const __nv_bfloat16* __restrict__ Al,
            const __nv_bfloat16* __restrict__ Bh, const __nv_bfloat16* __restrict__ Bl,
            float* __restrict__ Cf,
            int N, int K, int ldA, int ldB, size_t sA, size_t sB, size_t sC)
{
    extern __shared__ char smem[];
    const uint32_t sb = (smem_to_u32(smem) + 1023u) & ~1023u;
    const int tid = threadIdx.x;
    const int wid = tid >> 5;
    const int lane = tid & 31;
    const int z = blockIdx.z;
    const int rowBase = blockIdx.y * 128;
    const int colBase = blockIdx.x * 128;
    const int NC = K >> 6;

    const int warpRow = wid & 1;
    const int warpCol = wid >> 1;

    const __nv_bfloat16* aH = Ah + (size_t)z * sA + (size_t)rowBase * ldA;
    const __nv_bfloat16* aL = Al + (size_t)z * sA + (size_t)rowBase * ldA;
    const __nv_bfloat16* bH = Bh + (size_t)z * sB + (size_t)colBase * ldB;
    const __nv_bfloat16* bL = Bl + (size_t)z * sB + (size_t)colBase * ldB;

    const int grow0 = tid >> 3;
    const int kgB   = (tid & 7) * 16;
    const int kgE   = (tid & 7) * 8;

    auto load_chunk = [&](int stage, int chunk) {
        const uint32_t base = sb + stage * STAGE_BYTES;
        const int koff = chunk * 64 + kgE;
#pragma unroll
        for (int i = 0; i < 4; i++) {
            const int row = grow0 + i * 32;
            const uint32_t so = SWZ128((uint32_t)(row * 128 + kgB));
            cp16(base +         so, aH + (size_t)row * ldA + koff);
            cp16(base + 16384 + so, aL + (size_t)row * ldA + koff);
            cp16(base + 32768 + so, bH + (size_t)row * ldB + koff);
            cp16(base + 49152 + so, bL + (size_t)row * ldB + koff);
        }
        asm volatile("cp.async.commit_group;" ::: "memory");
    };

    float acc[4][4][4];
#pragma unroll
    for (int i = 0; i < 4; i++)
#pragma unroll
        for (int j = 0; j < 4; j++)
#pragma unroll
            for (int l = 0; l < 4; l++) acc[i][j][l] = 0.0f;

    const int aRow = warpRow * 64 + (lane & 15);
    const int aKB  = (lane >> 4) * 16;
    const int bRow = warpCol * 32 + ((lane >> 4) * 8) + (lane & 7);
    const int bKB  = ((lane >> 3) & 1) * 16;

    load_chunk(0, 0);
    if (NC > 1) load_chunk(1, 1);

    int s = 0;
    for (int c = 0; c < NC; c++) {
        if (c + 1 < NC) {
            asm volatile("cp.async.wait_group 1;" ::: "memory");
        } else {
            asm volatile("cp.async.wait_group 0;" ::: "memory");
        }
        __syncthreads();
        if (c + 2 < NC) {
            int s2 = s + 2; if (s2 >= 3) s2 -= 3;
            load_chunk(s2, c + 2);
        }

        const uint32_t st = sb + s * STAGE_BYTES;
#pragma unroll
        for (int ks = 0; ks < 4; ks++) {
            uint32_t ah[4][4], al[4][4], bh[4][2], bl[4][2];
#pragma unroll
            for (int mt = 0; mt < 4; mt++) {
                const uint32_t sw = SWZ128(
                    (uint32_t)((aRow + mt * 16) * 128 + ks * 32 + aKB));
                ldsm4(st + sw, ah[mt]);
                ldsm4(st + 16384 + sw, al[mt]);
            }
#pragma unroll
            for (int p = 0; p < 2; p++) {
                const uint32_t sw = SWZ128(
                    (uint32_t)((bRow + p * 16) * 128 + ks * 32 + bKB));
                uint32_t t[4];
                ldsm4(st + 32768 + sw, t);
                bh[2*p][0] = t[0]; bh[2*p][1] = t[1];
                bh[2*p+1][0] = t[2]; bh[2*p+1][1] = t[3];
                ldsm4(st + 49152 + sw, t);
                bl[2*p][0] = t[0]; bl[2*p][1] = t[1];
                bl[2*p+1][0] = t[2]; bl[2*p+1][1] = t[3];
            }
#pragma unroll
            for (int mt = 0; mt < 4; mt++)
#pragma unroll
                for (int nt = 0; nt < 4; nt++)
                    mma16816(acc[mt][nt], ah[mt], bh[nt]);
#pragma unroll
            for (int mt = 0; mt < 4; mt++)
#pragma unroll
                for (int nt = 0; nt < 4; nt++)
                    mma16816(acc[mt][nt], ah[mt], bl[nt]);
#pragma unroll
            for (int mt = 0; mt < 4; mt++)
#pragma unroll
                for (int nt = 0; nt < 4; nt++)
                    mma16816(acc[mt][nt], al[mt], bh[nt]);
        }
        if (++s == 3) s = 0;
    }

    const int lr = lane >> 2;
    const int lc = (lane & 3) * 2;
#pragma unroll
    for (int mt = 0; mt < 4; mt++) {
        const int r0 = rowBase + warpRow * 64 + mt * 16 + lr;
#pragma unroll
        for (int nt = 0; nt < 4; nt++) {
            const int c0 = colBase + warpCol * 32 + nt * 8 + lc;
            float* base = Cf + (size_t)z * sC;
            *reinterpret_cast<float2*>(&base[(size_t)r0 * N + c0]) =
                make_float2(acc[mt][nt][0], acc[mt][nt][1]);
            *reinterpret_cast<float2*>(&base[(size_t)(r0 + 8) * N + c0]) =
                make_float2(acc[mt][nt][2], acc[mt][nt][3]);
        }
    }
}

// ------------------------- fp16 GEMM (1-pass or 3-pass Dekker) --------------
template <int PASSES, int OUT_MODE, int BIAS_MODE>
__global__ void __launch_bounds__(256, (PASSES == 1 ? 2 : 1))
gemm_f16u(const __half* __restrict__ Ah, const __half* __restrict__ Al,
          const __half* __restrict__ Bh, const __half* __restrict__ Bl,
          const float* __restrict__ bias, float bscale, float oscale,
          float* __restrict__ Cf, __half* __restrict__ Ch, __half* __restrict__ Cl,
          int N, int K, int ldA, int ldB,
          size_t sA, size_t sB, size_t sC, size_t sBias)
{
    constexpr int STG  = (PASSES == 3) ? 65536 : 32768;
    constexpr int OFFB = (PASSES == 3) ? 32768 : 16384;
    extern __shared__ char smem[];
    const uint32_t sb = (smem_to_u32(smem) + 1023u) & ~1023u;
    const int tid = threadIdx.x;
    const int wid = tid >> 5;
    const int lane = tid & 31;
    const int z = blockIdx.z;
    const int rowBase = blockIdx.y * 128;
    const int colBase = blockIdx.x * 128;
    const int NC = K >> 6;

    const int warpRow = wid & 1;
    const int warpCol = wid >> 1;

    const __half* aH = Ah + (size_t)z * sA + (size_t)rowBase * ldA;
    const __half* aL = (PASSES == 3) ? (Al + (size_t)z * sA + (size_t)rowBase * ldA) : nullptr;
    const __half* bH = Bh + (size_t)z * sB + (size_t)colBase * ldB;
    const __half* bL = (PASSES == 3) ? (Bl + (size_t)z * sB + (size_t)colBase * ldB) : nullptr;

    const int grow0 = tid >> 3;
    const int kgB   = (tid & 7) * 16;
    const int kgE   = (tid & 7) * 8;

    auto load_chunk = [&](int stage, int chunk) {
        const uint32_t base = sb + stage * STG;
        const int koff = chunk * 64 + kgE;
#pragma unroll
        for (int i = 0; i < 4; i++) {
            const int row = grow0 + i * 32;
            const uint32_t so = SWZ128((uint32_t)(row * 128 + kgB));
            cp16(base + so, aH + (size_t)row * ldA + koff);
            if (PASSES == 3)
                cp16(base + 16384 + so, aL + (size_t)row * ldA + koff);
            cp16(base + OFFB + so, bH + (size_t)row * ldB + koff);
            if (PASSES == 3)
                cp16(base + OFFB + 16384 + so, bL + (size_t)row * ldB + koff);
        }
        asm volatile("cp.async.commit_group;" ::: "memory");
    };

    float acc[4][4][4];
#pragma unroll
    for (int i = 0; i < 4; i++)
#pragma unroll
        for (int j = 0; j < 4; j++)
#pragma unroll
            for (int l = 0; l < 4; l++) acc[i][j][l] = 0.0f;

    const int aRow = warpRow * 64 + (lane & 15);
    const int aKB  = (lane >> 4) * 16;
    const int bRow = warpCol * 32 + ((lane >> 4) * 8) + (lane & 7);
    const int bKB  = ((lane >> 3) & 1) * 16;

    load_chunk(0, 0);
    if (NC > 1) load_chunk(1, 1);

    int s = 0;
    for (int c = 0; c < NC; c++) {
        if (c + 1 < NC) {
            asm volatile("cp.async.wait_group 1;" ::: "memory");
        } else {
            asm volatile("cp.async.wait_group 0;" ::: "memory");
        }
        __syncthreads();
        if (c + 2 < NC) {
            int s2 = s + 2; if (s2 >= 3) s2 -= 3;
            load_chunk(s2, c + 2);
        }

        const uint32_t st = sb + s * STG;
#pragma unroll
        for (int ks = 0; ks < 4; ks++) {
            if (PASSES == 3) {
                uint32_t ah[4][4], al[4][4], bh[4][2], bl[4][2];
#pragma unroll
                for (int mt = 0; mt < 4; mt++) {
                    const uint32_t sw = SWZ128(
                        (uint32_t)((aRow + mt * 16) * 128 + ks * 32 + aKB));
                    ldsm4(st + sw, ah[mt]);
                    ldsm4(st + 16384 + sw, al[mt]);
                }
#pragma unroll
                for (int p = 0; p < 2; p++) {
                    const uint32_t sw = SWZ128(
                        (uint32_t)((bRow + p * 16) * 128 + ks * 32 + bKB));
                    uint32_t t[4];
                    ldsm4(st + OFFB + sw, t);
                    bh[2*p][0] = t[0]; bh[2*p][1] = t[1];
                    bh[2*p+1][0] = t[2]; bh[2*p+1][1] = t[3];
                    ldsm4(st + OFFB + 16384 + sw, t);
                    bl[2*p][0] = t[0]; bl[2*p][1] = t[1];
                    bl[2*p+1][0] = t[2]; bl[2*p+1][1] = t[3];
                }
#pragma unroll
                for (int mt = 0; mt < 4; mt++)
#pragma unroll
                    for (int nt = 0; nt < 4; nt++)
                        mma16816h(acc[mt][nt], ah[mt], bh[nt]);
#pragma unroll
                for (int mt = 0; mt < 4; mt++)
#pragma unroll
                    for (int nt = 0; nt < 4; nt++)
                        mma16816h(acc[mt][nt], ah[mt], bl[nt]);
#pragma unroll
                for (int mt = 0; mt < 4; mt++)
#pragma unroll
                    for (int nt = 0; nt < 4; nt++)
                        mma16816h(acc[mt][nt], al[mt], bh[nt]);
            } else {
                uint32_t bfr[4][2];
#pragma unroll
                for (int p = 0; p < 2; p++) {
                    const uint32_t sw = SWZ128(
                        (uint32_t)((bRow + p * 16) * 128 + ks * 32 + bKB));
                    uint32_t t[4];
                    ldsm4(st + OFFB + sw, t);
                    bfr[2*p][0] = t[0]; bfr[2*p][1] = t[1];
                    bfr[2*p+1][0] = t[2]; bfr[2*p+1][1] = t[3];
                }
#pragma unroll
                for (int mt = 0; mt < 4; mt++) {
                    const uint32_t sw = SWZ128(
                        (uint32_t)((aRow + mt * 16) * 128 + ks * 32 + aKB));
                    uint32_t ah[4];
                    ldsm4(st + sw, ah);
#pragma unroll
                    for (int nt = 0; nt < 4; nt++)
                        mma16816h(acc[mt][nt], ah, bfr[nt]);
                }
            }
        }
        if (++s == 3) s = 0;
    }

    const int lr = lane >> 2;
    const int lc = (lane & 3) * 2;
#pragma unroll
    for (int mt = 0; mt < 4; mt++) {
        const int r0 = rowBase + warpRow * 64 + mt * 16 + lr;
#pragma unroll
        for (int nt = 0; nt < 4; nt++) {
            const int c0 = colBase + warpCol * 32 + nt * 8 + lc;
            float v0 = acc[mt][nt][0], v1 = acc[mt][nt][1];
            float v2 = acc[mt][nt][2], v3 = acc[mt][nt][3];
            if (OUT_MODE == 0) {
                v0 *= oscale; v1 *= oscale; v2 *= oscale; v3 *= oscale;
                if (BIAS_MODE == 1) {
                    const float b0 = bias[z * sBias + c0];
                    const float b1 = bias[z * sBias + c0 + 1];
                    v0 += b0; v1 += b1; v2 += b0; v3 += b1;
                }
                float* base = Cf + (size_t)z * sC;
                *reinterpret_cast<float2*>(&base[(size_t)r0 * N + c0]) =
                    make_float2(v0, v1);
                *reinterpret_cast<float2*>(&base[(size_t)(r0 + 8) * N + c0]) =
                    make_float2(v2, v3);
            } else if (OUT_MODE == 1) {
                if (BIAS_MODE == 2) {
                    const float br0 = bias[r0] * bscale;
                    const float br8 = bias[r0 + 8] * bscale;
                    v0 += br0; v1 += br0; v2 += br8; v3 += br8;
                }
                __half* base = Ch + (size_t)z * sC;
                *reinterpret_cast<__half2*>(&base[(size_t)r0 * N + c0]) =
                    __floats2half2_rn(v0, v1);
                *reinterpret_cast<__half2*>(&base[(size_t)(r0 + 8) * N + c0]) =
                    __floats2half2_rn(v2, v3);
            } else {
                __half h0 = __float2half_rn(v0), h1 = __float2half_rn(v1);
                __half h2 = __float2half_rn(v2), h3 = __float2half_rn(v3);
                __half* chb = Ch + (size_t)z * sC;
                __half* clb = Cl + (size_t)z * sC;
                *reinterpret_cast<__half2*>(&chb[(size_t)r0 * N + c0]) =
                    __half2(h0, h1);
                *reinterpret_cast<__half2*>(&chb[(size_t)(r0 + 8) * N + c0]) =
                    __half2(h2, h3);
                *reinterpret_cast<__half2*>(&clb[(size_t)r0 * N + c0]) =
                    __half2(__float2half_rn(v0 - __half2float(h0)),
                            __float2half_rn(v1 - __half2float(h1)));
                *reinterpret_cast<__half2*>(&clb[(size_t)(r0 + 8) * N + c0]) =
                    __half2(__float2half_rn(v2 - __half2float(h2)),
                            __float2half_rn(v3 - __half2float(h3)));
            }
        }
    }
}

// ------------------------- launch ------------------------------------------
extern "C" void kernel_launch(void* const* d_in, const int* in_sizes, int n_in,
                              void* d_out, int out_size)
{
    (void)in_sizes; (void)n_in; (void)out_size;
    const float* x  = (const float*)d_in[0];
    const float* Wk = (const float*)d_in[1];
    const float* bk = (const float*)d_in[2];
    const float* Wq = (const float*)d_in[3];
    const float* bq = (const float*)d_in[4];  (void)bq;
    const float* Wv = (const float*)d_in[5];
    const float* bv = (const float*)d_in[6];
    float* out = (float*)d_out;

    __nv_bfloat16 *wkh, *wkl, *wqh, *wql;
    __half *xqh, *xql, *wvt16, *m16h, *m16l, *y16h, *y16l, *vt16, *ph;
    float *mp, *wv_, *tv, *sf;
    cudaGetSymbolAddress((void**)&xqh, g_xqh);   cudaGetSymbolAddress((void**)&xql, g_xql);
    cudaGetSymbolAddress((void**)&wkh, g_wkh);   cudaGetSymbolAddress((void**)&wkl, g_wkl);
    cudaGetSymbolAddress((void**)&wqh, g_wqh);   cudaGetSymbolAddress((void**)&wql, g_wql);
    cudaGetSymbolAddress((void**)&wvt16, g_wvt16);
    cudaGetSymbolAddress((void**)&mp, g_mp);
    cudaGetSymbolAddress((void**)&m16h, g_m16h); cudaGetSymbolAddress((void**)&m16l, g_m16l);
    cudaGetSymbolAddress((void**)&y16h, g_y16h); cudaGetSymbolAddress((void**)&y16l, g_y16l);
    cudaGetSymbolAddress((void**)&vt16, g_vt16);
    cudaGetSymbolAddress((void**)&wv_, g_w);     cudaGetSymbolAddress((void**)&tv, g_t);
    cudaGetSymbolAddress((void**)&sf, g_s);
    cudaGetSymbolAddress((void**)&ph, g_ph);

    cudaFuncSetAttribute(gemm_bf16x3, cudaFuncAttributeMaxDynamicSharedMemorySize, GEMM_SMEM);
    cudaFuncSetAttribute((const void*)gemm_f16u<1,1,2>,
                         cudaFuncAttributeMaxDynamicSharedMemorySize, 3 * 32768 + 1024);
    cudaFuncSetAttribute((const void*)gemm_f16u<1,0,0>,
                         cudaFuncAttributeMaxDynamicSharedMemorySize, 3 * 32768 + 1024);
    cudaFuncSetAttribute((const void*)gemm_f16u<3,2,0>,
                         cudaFuncAttributeMaxDynamicSharedMemorySize, 3 * 65536 + 1024);
    cudaFuncSetAttribute((const void*)gemm_f16u<3,0,1>,
                         cudaFuncAttributeMaxDynamicSharedMemorySize, 3 * 65536 + 1024);

    // Lazy one-time stream/event creation (first call is uncaptured).
    static cudaStream_t sB = nullptr;
    static cudaEvent_t e0 = nullptr, eX = nullptr, eB = nullptr,
                       eSm0 = nullptr, eP = nullptr;
    static bool multi = false;
    static bool tried = false;
    if (!tried) {
        tried = true;
        if (cudaStreamCreateWithFlags(&sB, cudaStreamNonBlocking) == cudaSuccess &&
            cudaEventCreateWithFlags(&e0, cudaEventDisableTiming) == cudaSuccess &&
            cudaEventCreateWithFlags(&eX, cudaEventDisableTiming) == cudaSuccess &&
            cudaEventCreateWithFlags(&eB, cudaEventDisableTiming) == cudaSuccess &&
            cudaEventCreateWithFlags(&eSm0, cudaEventDisableTiming) == cudaSuccess &&
            cudaEventCreateWithFlags(&eP, cudaEventDisableTiming) == cudaSuccess)
            multi = true;
    }
    cudaStream_t s1 = multi ? sB : (cudaStream_t)0;

    const int Mflat = BB * SEQ;  // 8192
    const size_t w4 = (size_t)EMB * EMB / 4;
    const size_t sXB = (size_t)SEQ * EMB;
    const size_t sSB = (size_t)SEQ * SEQ;

    // ---- stream A (origin): split2 first, then fork B ----
    split2_kernel<<<dim3((unsigned)((w4 + 255) / 256), 2), 256>>>(
        (const float4*)Wk, (const float4*)Wq,
        (__nv_bfloat162*)wkh, (__nv_bfloat162*)wkl,
        (__nv_bfloat162*)wqh, (__nv_bfloat162*)wql, w4);
    if (multi) {
        cudaEventRecord(e0, 0);
        cudaStreamWaitEvent(sB, e0, 0);   // legal fork: sB enters capture here
    }

    // ---- stream B: split_x -> Wv transpose -> wqbk -> vproj -> xw ----
    {
        size_t n4 = (size_t)Mflat * EMB / 4;
        split_x_kernel<<<(unsigned)((n4 + 255) / 256), 256, 0, s1>>>(
            (const float4*)x, (__half2*)xqh, (__half2*)xql, n4);
    }
    if (multi) cudaEventRecord(eX, sB);
    transpose_f16<<<dim3(32, 32, 1), dim3(32, 8), 0, s1>>>(Wv, wvt16, EMB, EMB);
    wqbk_kernel<<<EMB * 32 / 256, 256, 0, s1>>>(Wq, bk, wv_);
    gemm_f16u<1,1,2><<<dim3(16, 8, BB), 256, 3 * 32768 + 1024, s1>>>(
        wvt16, nullptr, xqh, nullptr, bv, 512.0f, 1.0f,
        nullptr, vt16, nullptr,
        SEQ, EMB, EMB, EMB, 0, sXB, (size_t)EMB * SEQ, 0);
    xw_kernel<<<Mflat * 32 / 256, 256, 0, s1>>>(x, wv_, tv);
    if (multi) cudaEventRecord(eB, sB);

    // ---- stream A: M' -> msum (no x dependence) ----
    gemm_bf16x3<<<dim3(8, 8, 2), 256, GEMM_SMEM>>>(
        wqh, wql, wkh, wkl, mp,
        EMB, 512, EMB, EMB, 512, 512, (size_t)EMB * EMB);
    msum_split_f16<<<(unsigned)((w4 + 255) / 256), 256>>>(
        (const float4*)mp, (const float4*)(mp + (size_t)EMB * EMB),
        (__half2*)m16h, (__half2*)m16l, w4);

    // y needs x split (B) + msum (A)
    if (multi) cudaStreamWaitEvent(0, eX, 0);
    gemm_f16u<3,2,0><<<dim3(8, 64, 1), 256, 3 * 65536 + 1024>>>(
        xqh, xql, m16h, m16l, nullptr, 0.0f, 1.0f,
        nullptr, y16h, y16l,
        EMB, EMB, EMB, EMB, 0, 0, 0, 0);

    // S needs y (A) + tv (B)
    if (multi) cudaStreamWaitEvent(0, eB, 0);
    gemm_f16u<3,0,1><<<dim3(16, 16, BB), 256, 3 * 65536 + 1024>>>(
        y16h, y16l, xqh, xql, tv, 0.0f, 1.0f,
        sf, nullptr, nullptr,
        SEQ, EMB, EMB, EMB, sXB, sXB, sSB, SEQ);

    if (multi) {
        // Tail: sm0 (A) -> [PV0 (A, tensor) || sm1 (B, fma/mem)] -> PV1 (B)
        softmax_poly<<<2 * SEQ, 256>>>(sf, (__half2*)ph);
        cudaEventRecord(eSm0, 0);
        cudaStreamWaitEvent(sB, eSm0, 0);
        softmax_poly<<<2 * SEQ, 256, 0, sB>>>(
            sf + 2 * sSB, (__half2*)(ph + 2 * sSB));
        gemm_f16u<1,0,0><<<dim3(8, 16, 2), 256, 3 * 32768 + 1024>>>(
            ph, nullptr, vt16, nullptr, nullptr, 0.0f, 1.0f / 512.0f,
            out, nullptr, nullptr,
            EMB, SEQ, SEQ, SEQ, sSB, (size_t)EMB * SEQ, sXB, 0);
        gemm_f16u<1,0,0><<<dim3(8, 16, 2), 256, 3 * 32768 + 1024, sB>>>(
            ph + 2 * sSB, nullptr, vt16 + 2 * sXB, nullptr,
            nullptr, 0.0f, 1.0f / 512.0f,
            out + 2 * sXB, nullptr, nullptr,
            EMB, SEQ, SEQ, SEQ, sSB, (size_t)EMB * SEQ, sXB, 0);
        cudaEventRecord(eP, sB);
        cudaStreamWaitEvent(0, eP, 0);
    } else {
        softmax_poly<<<BB * SEQ, 256>>>(sf, (__half2*)ph);
        gemm_f16u<1,0,0><<<dim3(8, 16, BB), 256, 3 * 32768 + 1024>>>(
            ph, nullptr, vt16, nullptr, nullptr, 0.0f, 1.0f / 512.0f,
            out, nullptr, nullptr,
            EMB, SEQ, SEQ, SEQ, sSB, (size_t)EMB * SEQ, sXB, 0);
    }
}